// round 4
// baseline (speedup 1.0000x reference)
#include <cuda_runtime.h>
#include <cstdint>

// MessagePassing: out[src[e], k] += edge_attrs_flat[k*E + e]
// edge_attrs: float32 [E*F] (values consumed as (F,E): contiguous in e per feature)
// attr_idx:   [2*E] ints (row 0 = src); int32 or int64, detected at runtime
// out:        float32 [N*F]

static constexpr int F = 16;

__device__ int g_idx_is64;   // 1 if indices are int64, 0 if int32

// Parallel dtype sniff: under little-endian int64, odd int32 words are high
// words of values < 2^32 -> all zero. 128 samples all zero => int64.
__global__ void detect_idx_kernel(const int* __restrict__ idx32, int n32) {
    __shared__ int not64;
    if (threadIdx.x == 0) not64 = 0;
    __syncthreads();
    int samples = 128;
    int stride = (n32 / 2) / samples;
    if (stride < 1) stride = 1;
    long long p = 2LL * (long long)threadIdx.x * stride + 1;  // high-word position
    if (p < n32 && idx32[p] != 0) not64 = 1;
    __syncthreads();
    if (threadIdx.x == 0) g_idx_is64 = !not64;
}

__global__ void zero_out_kernel(float4* __restrict__ out4, int n4) {
    int i = blockIdx.x * blockDim.x + threadIdx.x;
    if (i < n4) out4[i] = make_float4(0.f, 0.f, 0.f, 0.f);
}

// 4 edges per thread, float4 loads along e (contiguous per feature).
__global__ void __launch_bounds__(256)
scatter4_kernel(const float* __restrict__ attrs,
                const void* __restrict__ src_idx,
                float* __restrict__ out,
                int E, int n_groups) {
    int t = blockIdx.x * blockDim.x + threadIdx.x;
    if (t >= n_groups) return;

    int src[4];
    if (g_idx_is64) {
        const longlong2* p = (const longlong2*)src_idx + 2 * t;
        longlong2 a = p[0];
        longlong2 b = p[1];
        src[0] = (int)a.x; src[1] = (int)a.y;
        src[2] = (int)b.x; src[3] = (int)b.y;
    } else {
        int4 a = ((const int4*)src_idx)[t];
        src[0] = a.x; src[1] = a.y; src[2] = a.z; src[3] = a.w;
    }

    // v[k] = float4 of feature k for edges 4t..4t+3
    float4 v[F];
#pragma unroll
    for (int k = 0; k < F; k++) {
        v[k] = *(const float4*)(attrs + (size_t)k * (size_t)E + (size_t)(4 * t));
    }

    // Edge j uses component j of every v[k].
#pragma unroll
    for (int j = 0; j < 4; j++) {
        const float* vj = ((const float*)&v[0]) + j;  // stride 4 floats between ks
        float* dst = out + (size_t)src[j] * F;
#pragma unroll
        for (int kg = 0; kg < F; kg += 4) {
            asm volatile(
                "red.global.add.v4.f32 [%0], {%1, %2, %3, %4};"
                :: "l"(dst + kg),
                   "f"(vj[4 * (kg + 0)]), "f"(vj[4 * (kg + 1)]),
                   "f"(vj[4 * (kg + 2)]), "f"(vj[4 * (kg + 3)])
                : "memory");
        }
    }
}

// Scalar tail for E % 4 != 0 (not hit for E=4M, kept for correctness).
__global__ void scatter_tail_kernel(const float* __restrict__ attrs,
                                    const void* __restrict__ src_idx,
                                    float* __restrict__ out,
                                    int E, int e_begin) {
    int e = e_begin + blockIdx.x * blockDim.x + threadIdx.x;
    if (e >= E) return;
    int src = g_idx_is64 ? (int)((const long long*)src_idx)[e]
                         : ((const int*)src_idx)[e];
    float v[F];
#pragma unroll
    for (int k = 0; k < F; k++) v[k] = attrs[(size_t)k * (size_t)E + e];
    float* dst = out + (size_t)src * F;
#pragma unroll
    for (int kg = 0; kg < F; kg += 4) {
        asm volatile(
            "red.global.add.v4.f32 [%0], {%1, %2, %3, %4};"
            :: "l"(dst + kg), "f"(v[kg]), "f"(v[kg + 1]), "f"(v[kg + 2]), "f"(v[kg + 3])
            : "memory");
    }
}

extern "C" void kernel_launch(void* const* d_in, const int* in_sizes, int n_in,
                              void* d_out, int out_size) {
    const float* attrs = (const float*)d_in[0];
    const void* attr_idx = d_in[1];        // (2, E), row 0 = src
    float* out = (float*)d_out;

    int E = in_sizes[0] / F;
    int n_idx_elems = in_sizes[1];

    detect_idx_kernel<<<1, 128>>>((const int*)attr_idx, n_idx_elems);

    int n4 = out_size / 4;
    zero_out_kernel<<<(n4 + 255) / 256, 256>>>((float4*)out, n4);

    int n_groups = E / 4;
    if (n_groups > 0)
        scatter4_kernel<<<(n_groups + 255) / 256, 256>>>(attrs, attr_idx, out, E, n_groups);

    int rem_begin = n_groups * 4;
    int rem = E - rem_begin;
    if (rem > 0)
        scatter_tail_kernel<<<(rem + 255) / 256, 256>>>(attrs, attr_idx, out, E, rem_begin);
}